// round 13
// baseline (speedup 1.0000x reference)
#include <cuda_runtime.h>
#include <stdint.h>

// ---------------------------------------------------------------------------
// GAT layer (PyG GATConv semantics, add_self_loops=True).
// Passes: detect -> zero -> count -> gemm -> scan -> fill -> gather.
//   - gemm: h = x@W + attention dots (4-row-blocked, f32x2 FFMA2)
//   - CSR build: in-degree histogram, single-block scan, atomic-cursor fill
//     (fill also precomputes the 4 per-head exp numerators per edge)
//   - gather: warp per dst node; denominator summed in registers from stored
//     numerators; weighted accumulation of h[src]; single store of acc+bias.
// Softmax computed without max-shift (algebraically identical; logits bounded).
// ---------------------------------------------------------------------------

#define NN        100000
#define EE        1000000
#define TOT       (EE + NN)        // edges incl. self-loops
#define FEAT      128              // H*OUT
#define HH        4
#define NEG_SLOPE 0.2f
#define RPB       4                // rows per warp in GEMM

// 16B alignment REQUIRED where accessed as float4.
__device__ __align__(16) float  g_h[(size_t)NN * FEAT];     // 51.2 MB
__device__ __align__(16) float  g_asrc[(size_t)NN * HH];
__device__ __align__(16) float  g_adst[(size_t)NN * HH];
__device__ __align__(16) float4 g_cw[TOT];                  // exp numerators
__device__ int g_csrc[TOT];                                 // CSR src indices
__device__ int g_count[NN];
__device__ int g_rowptr[NN + 1];
__device__ int g_cursor[NN];
__device__ int g_is64;

__device__ __forceinline__ float leaky(float a) {
    return (a >= 0.f) ? a : NEG_SLOPE * a;
}

// ---- packed f32x2 helpers (Blackwell FFMA2 path, PTX-only) ----
__device__ __forceinline__ unsigned long long pack2(float a, float b) {
    unsigned long long r;
    asm("mov.b64 %0, {%1, %2};" : "=l"(r) : "f"(a), "f"(b));
    return r;
}
__device__ __forceinline__ unsigned long long ffma2(
        unsigned long long a, unsigned long long b, unsigned long long c) {
    unsigned long long d;
    asm("fma.rn.f32x2 %0, %1, %2, %3;" : "=l"(d) : "l"(a), "l"(b), "l"(c));
    return d;
}
__device__ __forceinline__ float2 unpack2(unsigned long long v) {
    float2 f;
    asm("mov.b64 {%0, %1}, %2;" : "=f"(f.x), "=f"(f.y) : "l"(v));
    return f;
}

// ---------------------------------------------------------------------------
__global__ void detect_kernel(const void* ei) {
    const unsigned long long* p = (const unsigned long long*)ei;
    int ok = 1;
    #pragma unroll
    for (int i = 0; i < 8; i++)
        if (p[i] >= (unsigned long long)NN) ok = 0;
    g_is64 = ok;
}

__global__ __launch_bounds__(256) void zero_kernel(int n) {
    const int i = blockIdx.x * blockDim.x + threadIdx.x;
    if (i < n) g_count[i] = 0;
}

// in-degree histogram (incl. self-loops)
__global__ __launch_bounds__(256) void count_kernel(
        const void* __restrict__ ei, long long E, int n) {
    const long long tot    = E + n;
    const long long stride = (long long)gridDim.x * blockDim.x;
    const int is64 = g_is64;
    for (long long e = (long long)blockIdx.x * blockDim.x + threadIdx.x;
         e < tot; e += stride) {
        int d;
        if (e < E) d = is64 ? (int)((const long long*)ei)[E + e]
                            : ((const int*)ei)[E + e];
        else       d = (int)(e - E);
        atomicAdd(&g_count[d], 1);
    }
}

// single-block exclusive scan: g_count[0..n) -> g_rowptr[0..n], g_cursor
__global__ __launch_bounds__(1024) void scan_kernel(int n) {
    __shared__ int s_wsum[32];
    __shared__ int s_total;
    __shared__ int s_carry;
    const int tid = threadIdx.x, lane = tid & 31, wid = tid >> 5;
    if (tid == 0) s_carry = 0;
    __syncthreads();

    for (int base = 0; base < n; base += 1024) {
        const int i = base + tid;
        const int v = (i < n) ? g_count[i] : 0;
        // inclusive warp scan
        int incl = v;
        #pragma unroll
        for (int off = 1; off < 32; off <<= 1) {
            int t = __shfl_up_sync(0xffffffffu, incl, off);
            if (lane >= off) incl += t;
        }
        if (lane == 31) s_wsum[wid] = incl;
        __syncthreads();
        if (wid == 0) {
            int w = s_wsum[lane];
            int wincl = w;
            #pragma unroll
            for (int off = 1; off < 32; off <<= 1) {
                int t = __shfl_up_sync(0xffffffffu, wincl, off);
                if (lane >= off) wincl += t;
            }
            s_wsum[lane] = wincl - w;          // exclusive warp offsets
            if (lane == 31) s_total = wincl;   // chunk total
        }
        __syncthreads();
        const int excl = s_carry + s_wsum[wid] + (incl - v);
        if (i < n) { g_rowptr[i] = excl; g_cursor[i] = excl; }
        __syncthreads();                       // all reads of s_carry done
        if (tid == 0) s_carry += s_total;
        __syncthreads();
    }
    if (tid == 0) g_rowptr[n] = s_carry;
}

// fill CSR: src index + 4 per-head exp numerators per edge
__global__ __launch_bounds__(256) void fill_kernel(
        const void* __restrict__ ei, long long E, int n) {
    const long long tot    = E + n;
    const long long stride = (long long)gridDim.x * blockDim.x;
    const int is64 = g_is64;
    for (long long e = (long long)blockIdx.x * blockDim.x + threadIdx.x;
         e < tot; e += stride) {
        int s, d;
        if (e < E) {
            if (is64) {
                s = (int)((const long long*)ei)[e];
                d = (int)((const long long*)ei)[E + e];
            } else {
                s = ((const int*)ei)[e];
                d = ((const int*)ei)[E + e];
            }
        } else { s = d = (int)(e - E); }

        const float4 as = ((const float4*)g_asrc)[s];
        const float4 ad = ((const float4*)g_adst)[d];
        float4 w;
        w.x = __expf(leaky(as.x + ad.x));
        w.y = __expf(leaky(as.y + ad.y));
        w.z = __expf(leaky(as.z + ad.z));
        w.w = __expf(leaky(as.w + ad.w));
        const int pos = atomicAdd(&g_cursor[d], 1);
        g_csrc[pos] = s;
        g_cw[pos]   = w;
    }
}

// ---------------------------------------------------------------------------
// GEMM + attention dots. 8 warps/block, RPB=4 rows per warp per iteration.
// W staged in smem (64KB), read once per 4 rows (ulonglong2 = 2 f32x2 ops).
__global__ __launch_bounds__(256, 2) void gemm_att_kernel(
        const float* __restrict__ x, const float* __restrict__ W,
        const float* __restrict__ att_src, const float* __restrict__ att_dst,
        int n) {
    extern __shared__ float sm[];
    float* Ws = sm;                      // FEAT*FEAT
    float* xs = sm + FEAT * FEAT;        // 8 * RPB * FEAT
    __shared__ float s_as[FEAT], s_ad[FEAT];

    for (int i = threadIdx.x; i < FEAT * FEAT / 4; i += blockDim.x)
        ((float4*)Ws)[i] = ((const float4*)W)[i];
    if (threadIdx.x < FEAT) {
        s_as[threadIdx.x] = att_src[threadIdx.x];
        s_ad[threadIdx.x] = att_dst[threadIdx.x];
    }
    __syncthreads();

    const int warp = threadIdx.x >> 5;
    const int lane = threadIdx.x & 31;
    float* xw = xs + warp * (RPB * FEAT);
    const ulonglong2* Ws2 = (const ulonglong2*)Ws;

    const long long base = ((long long)blockIdx.x * 8 + warp) * RPB;
    const long long step = (long long)gridDim.x * 8 * RPB;

    for (long long row0 = base; row0 < n; row0 += step) {
        const int nr = (int)((n - row0 < RPB) ? (n - row0) : RPB);
        #pragma unroll
        for (int r = 0; r < RPB; r++)
            if (r < nr)
                ((float4*)(xw + r * FEAT))[lane] =
                    ((const float4*)(x + (row0 + r) * FEAT))[lane];
        __syncwarp();

        unsigned long long acc[RPB][2];
        #pragma unroll
        for (int r = 0; r < RPB; r++) { acc[r][0] = 0ull; acc[r][1] = 0ull; }

        for (int k = 0; k < FEAT; k += 4) {
            float4 xv[RPB];
            #pragma unroll
            for (int r = 0; r < RPB; r++)
                xv[r] = *((const float4*)(xw + r * FEAT + k));
            #pragma unroll
            for (int kk = 0; kk < 4; kk++) {
                const ulonglong2 w2 = Ws2[(k + kk) * (FEAT / 4) + lane];
                #pragma unroll
                for (int r = 0; r < RPB; r++) {
                    const float xr = (kk == 0) ? xv[r].x :
                                     (kk == 1) ? xv[r].y :
                                     (kk == 2) ? xv[r].z : xv[r].w;
                    const unsigned long long xx = pack2(xr, xr);
                    acc[r][0] = ffma2(xx, w2.x, acc[r][0]);
                    acc[r][1] = ffma2(xx, w2.y, acc[r][1]);
                }
            }
        }

        #pragma unroll
        for (int r = 0; r < RPB; r++) {
            if (r >= nr) break;
            const float2 lo = unpack2(acc[r][0]);
            const float2 hi = unpack2(acc[r][1]);
            const long long row = row0 + r;
            ((float4*)(g_h + row * FEAT))[lane] =
                make_float4(lo.x, lo.y, hi.x, hi.y);

            const int cb = lane * 4;
            float ps = lo.x * s_as[cb] + lo.y * s_as[cb + 1] +
                       hi.x * s_as[cb + 2] + hi.y * s_as[cb + 3];
            float pd = lo.x * s_ad[cb] + lo.y * s_ad[cb + 1] +
                       hi.x * s_ad[cb + 2] + hi.y * s_ad[cb + 3];
            #pragma unroll
            for (int off = 4; off >= 1; off >>= 1) {
                ps += __shfl_down_sync(0xffffffffu, ps, off, 8);
                pd += __shfl_down_sync(0xffffffffu, pd, off, 8);
            }
            if ((lane & 7) == 0) {
                const int head = lane >> 3;
                g_asrc[row * HH + head] = ps;
                g_adst[row * HH + head] = pd;
            }
        }
        __syncwarp();
    }
}

// ---------------------------------------------------------------------------
// Gather: warp per dst node (grid-stride). Loop 1 sums the stored exp
// numerators (lane-strided, butterfly-reduced) -> per-head reciprocal on
// lanes 0-3, shfl-broadcast. Loop 2 accumulates w*h[src] in registers.
// One coalesced store of acc + bias per node. No atomics.
__global__ __launch_bounds__(256) void gather_kernel(
        const float* __restrict__ bias, int n, float* __restrict__ out) {
    const int lane = threadIdx.x & 31;
    const int head = lane >> 3;
    const long long wstride = ((long long)gridDim.x * blockDim.x) >> 5;
    const float4 b4 = ((const float4*)bias)[lane];

    for (long long d = ((long long)blockIdx.x * blockDim.x + threadIdx.x) >> 5;
         d < n; d += wstride) {
        const int start = g_rowptr[d];
        const int end   = g_rowptr[d + 1];

        // loop 1: denominator (sum of stored numerators)
        float4 ds = make_float4(0.f, 0.f, 0.f, 0.f);
        for (int i = start + lane; i < end; i += 32) {
            const float4 wv = g_cw[i];
            ds.x += wv.x; ds.y += wv.y; ds.z += wv.z; ds.w += wv.w;
        }
        #pragma unroll
        for (int off = 16; off >= 1; off >>= 1) {
            ds.x += __shfl_xor_sync(0xffffffffu, ds.x, off);
            ds.y += __shfl_xor_sync(0xffffffffu, ds.y, off);
            ds.z += __shfl_xor_sync(0xffffffffu, ds.z, off);
            ds.w += __shfl_xor_sync(0xffffffffu, ds.w, off);
        }
        float rd = 0.f;
        if (lane < HH) {
            const float dv = (lane == 0) ? ds.x : (lane == 1) ? ds.y :
                             (lane == 2) ? ds.z : ds.w;
            rd = 1.0f / (dv + 1e-16f);
        }
        const float rdh = __shfl_sync(0xffffffffu, rd, head);

        // loop 2: weighted accumulation of h[src]
        float4 acc = make_float4(0.f, 0.f, 0.f, 0.f);
        for (int i = start; i < end; i++) {
            const int s = g_csrc[i];
            const float4 wv = g_cw[i];
            const float w = ((head == 0) ? wv.x : (head == 1) ? wv.y :
                             (head == 2) ? wv.z : wv.w) * rdh;
            const float4 hv = ((const float4*)(g_h + (size_t)s * FEAT))[lane];
            acc.x += w * hv.x; acc.y += w * hv.y;
            acc.z += w * hv.z; acc.w += w * hv.w;
        }
        ((float4*)(out + (size_t)d * FEAT))[lane] =
            make_float4(acc.x + b4.x, acc.y + b4.y,
                        acc.z + b4.z, acc.w + b4.w);
    }
}

// ---------------------------------------------------------------------------
extern "C" void kernel_launch(void* const* d_in, const int* in_sizes, int n_in,
                              void* d_out, int out_size) {
    const float* x       = (const float*)d_in[0];
    const void*  ei      = d_in[1];
    const float* W       = (const float*)d_in[2];
    const float* att_src = (const float*)d_in[3];
    const float* att_dst = (const float*)d_in[4];
    const float* bias    = (const float*)d_in[5];
    float* out = (float*)d_out;

    const int       n = in_sizes[0] / FEAT;         // 100000
    const long long E = (long long)in_sizes[1] / 2; // 1000000

    detect_kernel<<<1, 1>>>(ei);
    zero_kernel<<<(n + 255) / 256, 256>>>(n);
    count_kernel<<<148 * 8, 256>>>(ei, E, n);

    {
        const int smem = (FEAT * FEAT + 8 * RPB * FEAT) * (int)sizeof(float);
        cudaFuncSetAttribute(gemm_att_kernel,
                             cudaFuncAttributeMaxDynamicSharedMemorySize, smem);
        gemm_att_kernel<<<296, 256, smem>>>(x, W, att_src, att_dst, n);
    }

    scan_kernel<<<1, 1024>>>(n);
    fill_kernel<<<148 * 8, 256>>>(ei, E, n);
    gather_kernel<<<148 * 16, 256>>>(bias, n, out);
}

// round 17
// speedup vs baseline: 1.1644x; 1.1644x over previous
#include <cuda_runtime.h>
#include <stdint.h>

// ---------------------------------------------------------------------------
// GAT layer (PyG GATConv semantics, add_self_loops=True).
// Passes: detect -> init -> gemm (2-row-blocked, f32x2 FFMA2, 3 blocks/SM) ->
//         esum -> recip -> escat.   (CSR variant benched SLOWER; reverted.)
// Softmax computed without max-shift (algebraically identical; logits bounded).
// ---------------------------------------------------------------------------

#define NN        100000
#define FEAT      128      // H*OUT
#define HH        4
#define NEG_SLOPE 0.2f
#define RPB       2        // rows per warp in GEMM (smem 72KB -> 3 blocks/SM)

// 16B alignment REQUIRED: accessed as float4 / ulonglong2 / red.add.v4.
__device__ __align__(16) float g_h[(size_t)NN * FEAT];     // 51.2 MB
__device__ __align__(16) float g_asrc[(size_t)NN * HH];
__device__ __align__(16) float g_adst[(size_t)NN * HH];
__device__ __align__(16) float g_denom[(size_t)NN * HH];   // later: reciprocal
__device__ int g_is64;

__device__ __forceinline__ float leaky(float a) {
    return (a >= 0.f) ? a : NEG_SLOPE * a;
}

// ---- packed f32x2 helpers (Blackwell FFMA2 path, PTX-only) ----
__device__ __forceinline__ unsigned long long pack2(float a, float b) {
    unsigned long long r;
    asm("mov.b64 %0, {%1, %2};" : "=l"(r) : "f"(a), "f"(b));
    return r;
}
__device__ __forceinline__ unsigned long long ffma2(
        unsigned long long a, unsigned long long b, unsigned long long c) {
    unsigned long long d;
    asm("fma.rn.f32x2 %0, %1, %2, %3;" : "=l"(d) : "l"(a), "l"(b), "l"(c));
    return d;
}
__device__ __forceinline__ float2 unpack2(unsigned long long v) {
    float2 f;
    asm("mov.b64 {%0, %1}, %2;" : "=f"(f.x), "=f"(f.y) : "l"(v));
    return f;
}

// ---------------------------------------------------------------------------
__global__ void detect_kernel(const void* ei) {
    const unsigned long long* p = (const unsigned long long*)ei;
    int ok = 1;
    #pragma unroll
    for (int i = 0; i < 8; i++)
        if (p[i] >= (unsigned long long)NN) ok = 0;
    g_is64 = ok;
}

__global__ __launch_bounds__(256) void init_kernel(
        const float* __restrict__ bias, int n, float* __restrict__ out) {
    long long total = (long long)n * FEAT;
    for (long long i = (long long)blockIdx.x * blockDim.x + threadIdx.x;
         i < total; i += (long long)gridDim.x * blockDim.x) {
        out[i] = bias[(int)(i & (FEAT - 1))];
        if (i < (long long)n * HH) g_denom[i] = 0.0f;
    }
}

// ---------------------------------------------------------------------------
// GEMM + attention dots. 8 warps/block, RPB=2 rows per warp per iteration.
// W staged in smem (64KB) + x rows (8*2*128 floats = 8KB) = 72KB -> 3 blk/SM.
__global__ __launch_bounds__(256, 3) void gemm_att_kernel(
        const float* __restrict__ x, const float* __restrict__ W,
        const float* __restrict__ att_src, const float* __restrict__ att_dst,
        int n) {
    extern __shared__ float sm[];
    float* Ws = sm;                      // FEAT*FEAT
    float* xs = sm + FEAT * FEAT;        // 8 * RPB * FEAT
    __shared__ float s_as[FEAT], s_ad[FEAT];

    for (int i = threadIdx.x; i < FEAT * FEAT / 4; i += blockDim.x)
        ((float4*)Ws)[i] = ((const float4*)W)[i];
    if (threadIdx.x < FEAT) {
        s_as[threadIdx.x] = att_src[threadIdx.x];
        s_ad[threadIdx.x] = att_dst[threadIdx.x];
    }
    __syncthreads();

    const int warp = threadIdx.x >> 5;
    const int lane = threadIdx.x & 31;
    float* xw = xs + warp * (RPB * FEAT);
    const ulonglong2* Ws2 = (const ulonglong2*)Ws;   // [k][lane] 16B granules

    const long long base = ((long long)blockIdx.x * 8 + warp) * RPB;
    const long long step = (long long)gridDim.x * 8 * RPB;

    for (long long row0 = base; row0 < n; row0 += step) {
        const int nr = (int)((n - row0 < RPB) ? (n - row0) : RPB);
        #pragma unroll
        for (int r = 0; r < RPB; r++)
            if (r < nr)
                ((float4*)(xw + r * FEAT))[lane] =
                    ((const float4*)(x + (row0 + r) * FEAT))[lane];
        __syncwarp();

        // acc[r][0] = cols (lane*4+0, +1); acc[r][1] = (+2, +3)
        unsigned long long acc[RPB][2];
        #pragma unroll
        for (int r = 0; r < RPB; r++) { acc[r][0] = 0ull; acc[r][1] = 0ull; }

        for (int k = 0; k < FEAT; k += 4) {
            float4 xv[RPB];
            #pragma unroll
            for (int r = 0; r < RPB; r++)
                xv[r] = *((const float4*)(xw + r * FEAT + k));   // broadcast
            #pragma unroll
            for (int kk = 0; kk < 4; kk++) {
                const ulonglong2 w2 = Ws2[(k + kk) * (FEAT / 4) + lane];
                #pragma unroll
                for (int r = 0; r < RPB; r++) {
                    const float xr = (kk == 0) ? xv[r].x :
                                     (kk == 1) ? xv[r].y :
                                     (kk == 2) ? xv[r].z : xv[r].w;
                    const unsigned long long xx = pack2(xr, xr);
                    acc[r][0] = ffma2(xx, w2.x, acc[r][0]);
                    acc[r][1] = ffma2(xx, w2.y, acc[r][1]);
                }
            }
        }

        #pragma unroll
        for (int r = 0; r < RPB; r++) {
            if (r >= nr) break;
            const float2 lo = unpack2(acc[r][0]);
            const float2 hi = unpack2(acc[r][1]);
            const long long row = row0 + r;
            ((float4*)(g_h + row * FEAT))[lane] =
                make_float4(lo.x, lo.y, hi.x, hi.y);

            // attention dots: lane covers channels [lane*4, +4); head=lane/8;
            // reduce partials over 8-lane groups.
            const int cb = lane * 4;
            float ps = lo.x * s_as[cb] + lo.y * s_as[cb + 1] +
                       hi.x * s_as[cb + 2] + hi.y * s_as[cb + 3];
            float pd = lo.x * s_ad[cb] + lo.y * s_ad[cb + 1] +
                       hi.x * s_ad[cb + 2] + hi.y * s_ad[cb + 3];
            #pragma unroll
            for (int off = 4; off >= 1; off >>= 1) {
                ps += __shfl_down_sync(0xffffffffu, ps, off, 8);
                pd += __shfl_down_sync(0xffffffffu, pd, off, 8);
            }
            if ((lane & 7) == 0) {
                const int head = lane >> 3;
                g_asrc[row * HH + head] = ps;
                g_adst[row * HH + head] = pd;
            }
        }
        __syncwarp();   // protect xw reuse
    }
}

// ---------------------------------------------------------------------------
// Denominator pass: 1 thread per edge (grid-stride), all 4 heads vectorized.
__global__ __launch_bounds__(256) void edge_sum_kernel(
        const void* __restrict__ ei, long long E, int n) {
    const long long tot    = E + n;
    const long long stride = (long long)gridDim.x * blockDim.x;
    const int is64 = g_is64;

    for (long long e = (long long)blockIdx.x * blockDim.x + threadIdx.x;
         e < tot; e += stride) {
        int s, d;
        if (e < E) {
            if (is64) {
                s = (int)((const long long*)ei)[e];
                d = (int)((const long long*)ei)[E + e];
            } else {
                s = ((const int*)ei)[e];
                d = ((const int*)ei)[E + e];
            }
        } else { s = d = (int)(e - E); }

        const float4 as = ((const float4*)g_asrc)[s];
        const float4 ad = ((const float4*)g_adst)[d];
        float e0 = __expf(leaky(as.x + ad.x));
        float e1 = __expf(leaky(as.y + ad.y));
        float e2 = __expf(leaky(as.z + ad.z));
        float e3 = __expf(leaky(as.w + ad.w));
        float* dst = g_denom + (size_t)d * HH;
        asm volatile("red.global.add.v4.f32 [%0], {%1, %2, %3, %4};"
                     :: "l"(dst), "f"(e0), "f"(e1), "f"(e2), "f"(e3)
                     : "memory");
    }
}

__global__ __launch_bounds__(256) void recip_kernel(int n) {
    const long long tot = (long long)n * HH;
    const long long i = (long long)blockIdx.x * blockDim.x + threadIdx.x;
    if (i < tot) g_denom[i] = 1.0f / (g_denom[i] + 1e-16f);
}

// ---------------------------------------------------------------------------
// Scatter: one warp per edge (grid-stride over warps). Lanes 0-3 compute the
// 4 per-head weights (4 expf/edge instead of 32); shfl-broadcast; lane handles
// 4 contiguous channels. red.global.add.v4.f32 (no return).
__global__ __launch_bounds__(256) void edge_scatter_kernel(
        const void* __restrict__ ei, long long E, int n,
        float* __restrict__ out) {
    const long long tot     = E + n;
    const long long wstride = ((long long)gridDim.x * blockDim.x) >> 5;
    const int lane = threadIdx.x & 31;
    const int head = lane >> 3;
    const int is64 = g_is64;

    for (long long e = ((long long)blockIdx.x * blockDim.x + threadIdx.x) >> 5;
         e < tot; e += wstride) {
        int s, d;
        if (e < E) {
            if (is64) {
                s = (int)((const long long*)ei)[e];
                d = (int)((const long long*)ei)[E + e];
            } else {
                s = ((const int*)ei)[e];
                d = ((const int*)ei)[E + e];
            }
        } else { s = d = (int)(e - E); }

        float wv = 0.f;
        if (lane < HH) {
            const float a = leaky(__ldg(&g_asrc[(size_t)s * HH + lane]) +
                                  __ldg(&g_adst[(size_t)d * HH + lane]));
            wv = __expf(a) * __ldg(&g_denom[(size_t)d * HH + lane]);
        }
        const float w = __shfl_sync(0xffffffffu, wv, head);

        const float4 hv = ((const float4*)(g_h + (size_t)s * FEAT))[lane];
        float* dst = out + (size_t)d * FEAT + lane * 4;
        asm volatile("red.global.add.v4.f32 [%0], {%1, %2, %3, %4};"
                     :: "l"(dst), "f"(hv.x * w), "f"(hv.y * w),
                        "f"(hv.z * w), "f"(hv.w * w)
                     : "memory");
    }
}

// ---------------------------------------------------------------------------
extern "C" void kernel_launch(void* const* d_in, const int* in_sizes, int n_in,
                              void* d_out, int out_size) {
    const float* x       = (const float*)d_in[0];
    const void*  ei      = d_in[1];
    const float* W       = (const float*)d_in[2];
    const float* att_src = (const float*)d_in[3];
    const float* att_dst = (const float*)d_in[4];
    const float* bias    = (const float*)d_in[5];
    float* out = (float*)d_out;

    const int       n = in_sizes[0] / FEAT;         // 100000
    const long long E = (long long)in_sizes[1] / 2; // 1000000

    detect_kernel<<<1, 1>>>(ei);

    init_kernel<<<2048, 256>>>(bias, n, out);

    {
        const int smem = (FEAT * FEAT + 8 * RPB * FEAT) * (int)sizeof(float); // 73728
        cudaFuncSetAttribute(gemm_att_kernel,
                             cudaFuncAttributeMaxDynamicSharedMemorySize, smem);
        gemm_att_kernel<<<444, 256, smem>>>(x, W, att_src, att_dst, n);
    }

    edge_sum_kernel<<<148 * 8, 256>>>(ei, E, n);

    {
        int threads = 256;
        long long blocks = ((long long)n * HH + threads - 1) / threads;
        recip_kernel<<<(unsigned)blocks, threads>>>(n);
    }

    edge_scatter_kernel<<<148 * 64, 256>>>(ei, E, n, out);
}